// round 6
// baseline (speedup 1.0000x reference)
#include <cuda_runtime.h>
#include <cuda_fp16.h>
#include <cstdint>

// MeanAggregator: out[b, :] = mean_k features[neigh_idx[b, k], :]
// B=16384, K=15, U=19997, D=256 (idx int32 on device)
//
// Pass 1: fp32 table -> fp16 shadow (64B per thread, STG.128 stores).
// Pass 2: gather fp16 rows, 2 rows per warp (30 outstanding LDG.128 per
// lane) with fp32 accumulation; fp32 output.

#define K_NEIGH 15
#define D_DIM 256
#define U_ROWS 19997
#define WARPS_PER_BLOCK 8
#define ROWS_PER_WARP 2
#define ROWS_PER_BLOCK (WARPS_PER_BLOCK * ROWS_PER_WARP)

__device__ __half g_feat_h[(size_t)U_ROWS * D_DIM];

// ---- Pass 1: fp32 -> fp16, 16 floats (64B in / 32B out) per thread ----
__global__ __launch_bounds__(256)
void convert_kernel(const float* __restrict__ f, int n16)
{
    int i = blockIdx.x * blockDim.x + threadIdx.x;
    if (i >= n16) return;

    const float4* src = reinterpret_cast<const float4*>(f) + (size_t)i * 4;
    uint4 d[2];
    __half2* h = reinterpret_cast<__half2*>(d);
    #pragma unroll
    for (int j = 0; j < 4; ++j) {
        float4 v = src[j];
        h[j * 2 + 0] = __floats2half2_rn(v.x, v.y);
        h[j * 2 + 1] = __floats2half2_rn(v.z, v.w);
    }
    uint4* dst = reinterpret_cast<uint4*>(g_feat_h) + (size_t)i * 2;
    dst[0] = d[0];
    dst[1] = d[1];
}

// ---- Pass 2: gather + mean, 2 rows per warp ----
__global__ __launch_bounds__(256)
void gather_kernel(const int* __restrict__ neigh_idx,
                   float* __restrict__ out,
                   int B)
{
    __shared__ int sidx[ROWS_PER_BLOCK][K_NEIGH + 1];

    const int tid  = threadIdx.x;
    const int warp = tid >> 5;
    const int lane = tid & 31;
    const int row0 = blockIdx.x * ROWS_PER_BLOCK;

    // 240 index loads by 256 threads
    if (tid < ROWS_PER_BLOCK * K_NEIGH) {
        const int r = tid / K_NEIGH, c = tid % K_NEIGH;
        if (row0 + r < B) sidx[r][c] = neigh_idx[(row0 + r) * K_NEIGH + c];
    }
    __syncthreads();

    const int ra = row0 + warp * ROWS_PER_WARP;      // first of this warp's 2 rows
    const int rb = ra + 1;
    if (ra >= B) return;
    const bool has_b = (rb < B);

    const uint4* __restrict__ f = reinterpret_cast<const uint4*>(g_feat_h);

    float accA[8] = {0,0,0,0,0,0,0,0};
    float accB[8] = {0,0,0,0,0,0,0,0};

    #pragma unroll
    for (int k = 0; k < K_NEIGH; ++k) {
        const int ida = sidx[warp * ROWS_PER_WARP + 0][k];
        const int idb = has_b ? sidx[warp * ROWS_PER_WARP + 1][k] : ida;

        const uint4 va = f[ida * (D_DIM / 8) + lane];
        const uint4 vb = f[idb * (D_DIM / 8) + lane];

        const __half2* ha = reinterpret_cast<const __half2*>(&va);
        const __half2* hb = reinterpret_cast<const __half2*>(&vb);
        #pragma unroll
        for (int j = 0; j < 4; ++j) {
            float2 fa = __half22float2(ha[j]);
            float2 fb = __half22float2(hb[j]);
            accA[j * 2]     += fa.x; accA[j * 2 + 1] += fa.y;
            accB[j * 2]     += fb.x; accB[j * 2 + 1] += fb.y;
        }
    }

    const float inv = 1.0f / (float)K_NEIGH;

    {
        float4 o0 = make_float4(accA[0]*inv, accA[1]*inv, accA[2]*inv, accA[3]*inv);
        float4 o1 = make_float4(accA[4]*inv, accA[5]*inv, accA[6]*inv, accA[7]*inv);
        float4* op = reinterpret_cast<float4*>(out + (size_t)ra * D_DIM + lane * 8);
        op[0] = o0; op[1] = o1;
    }
    if (has_b) {
        float4 o0 = make_float4(accB[0]*inv, accB[1]*inv, accB[2]*inv, accB[3]*inv);
        float4 o1 = make_float4(accB[4]*inv, accB[5]*inv, accB[6]*inv, accB[7]*inv);
        float4* op = reinterpret_cast<float4*>(out + (size_t)rb * D_DIM + lane * 8);
        op[0] = o0; op[1] = o1;
    }
}

extern "C" void kernel_launch(void* const* d_in, const int* in_sizes, int n_in,
                              void* d_out, int out_size)
{
    int idx_slot = 0, feat_slot = 1;
    if (n_in >= 2 && in_sizes[0] > in_sizes[1]) { idx_slot = 1; feat_slot = 0; }

    const int*   neigh_idx = (const int*)d_in[idx_slot];     // [B, K] int32
    const float* features  = (const float*)d_in[feat_slot];  // [U, D] fp32
    float*       out       = (float*)d_out;                  // [B, D] fp32

    const int B      = in_sizes[idx_slot] / K_NEIGH;
    const int n_feat = in_sizes[feat_slot];                  // U * D, divisible by 16
    const int n16    = n_feat / 16;

    convert_kernel<<<(n16 + 255) / 256, 256>>>(features, n16);

    dim3 block(WARPS_PER_BLOCK * 32);
    dim3 grid((B + ROWS_PER_BLOCK - 1) / ROWS_PER_BLOCK);
    gather_kernel<<<grid, block>>>(neigh_idx, out, B);
}